// round 14
// baseline (speedup 1.0000x reference)
#include <cuda_runtime.h>
#include <cstdint>

#define SEQ 43
#define DIM 18
#define NLAYERS 6
#define HEADS 3
#define DKH 6
#define DFF 2048
#define BATCH 256
#define AMAX 128
#define NB 7
#define NROWS (BATCH*SEQ)   /* 11008 = 86*128 */
#define LNEPS 1e-6f

#define FSPLIT 8             /* f-splits for ff grid.y */
#define FBLK 256             /* f per block */
#define FCH 128              /* f per staging chunk (2 chunks per block) */

typedef unsigned int uint32;

__device__ float g_bufA[NROWS*DIM];
__device__ float g_bufB[NROWS*DIM];
__device__ float g_M1[SEQ*NB], g_M2[SEQ*NB];
__device__ float g_S1[NB], g_S2[NB], g_c1[NB], g_c2[NB];

__device__ __forceinline__ uint32 tf32cvt(float f){
    uint32 u; asm("cvt.rna.tf32.f32 %0, %1;" : "=r"(u) : "f"(f)); return u;
}

#define MMA_TF32(d0,d1,d2,d3,a0,a1,a2,a3,b0,b1)                          \
    asm volatile("mma.sync.aligned.m16n8k8.row.col.f32.tf32.tf32.f32 "   \
        "{%0,%1,%2,%3}, {%4,%5,%6,%7}, {%8,%9}, {%0,%1,%2,%3};"          \
        : "+f"(d0), "+f"(d1), "+f"(d2), "+f"(d3)                          \
        : "r"(a0), "r"(a1), "r"(a2), "r"(a3), "r"(b0), "r"(b1))

/* The R10-proven per-chunk MMA loop, as a macro so accumulators stay in regs */
#define MMA_CHUNK() do {                                                     \
    for (int f8 = 0; f8 < FCH/8; f8++){                                      \
        const int fo = f8*8;                                                 \
        uint32 bA[3][2];                                                     \
        _Pragma("unroll")                                                    \
        for (int ks = 0; ks < 3; ks++){                                      \
            bA[ks][0] = w1s[(8*ks + q)*136 + fo + g];                        \
            bA[ks][1] = w1s[(8*ks + q + 4)*136 + fo + g];                    \
        }                                                                    \
        uint32 bB[3][2];                                                     \
        _Pragma("unroll")                                                    \
        for (int np = 0; np < 3; np++){                                      \
            bB[np][0] = w2t[(np*8 + g)*132 + fo + q];                        \
            bB[np][1] = w2t[(np*8 + g)*132 + fo + q + 4];                    \
        }                                                                    \
        const float hb0 = b1s[fo + 2*q], hb1 = b1s[fo + 2*q + 1];            \
        _Pragma("unroll")                                                    \
        for (int ms = 0; ms < 2; ms++){                                      \
            float h0 = hb0, h1 = hb1, h2 = hb0, h3 = hb1;                    \
            _Pragma("unroll")                                                \
            for (int ks = 0; ks < 3; ks++)                                   \
                MMA_TF32(h0, h1, h2, h3,                                     \
                         aU[ms][ks][0], aU[ms][ks][1], aU[ms][ks][2],        \
                         aU[ms][ks][3], bA[ks][0], bA[ks][1]);               \
            h0 = fmaxf(h0, 0.f); h1 = fmaxf(h1, 0.f);                        \
            h2 = fmaxf(h2, 0.f); h3 = fmaxf(h3, 0.f);                        \
            uint32 u0 = tf32cvt(h0), u1 = tf32cvt(h1);                       \
            uint32 u2 = tf32cvt(h2), u3 = tf32cvt(h3);                       \
            const int s0 = (lane & ~3) | (q >> 1);                           \
            const int s1 = s0 + 2;                                           \
            uint32 t00 = __shfl_sync(0xffffffffu, u0, s0);                   \
            uint32 t01 = __shfl_sync(0xffffffffu, u1, s0);                   \
            uint32 t02 = __shfl_sync(0xffffffffu, u2, s0);                   \
            uint32 t03 = __shfl_sync(0xffffffffu, u3, s0);                   \
            uint32 t10 = __shfl_sync(0xffffffffu, u0, s1);                   \
            uint32 t11 = __shfl_sync(0xffffffffu, u1, s1);                   \
            uint32 t12 = __shfl_sync(0xffffffffu, u2, s1);                   \
            uint32 t13 = __shfl_sync(0xffffffffu, u3, s1);                   \
            const bool par = (q & 1);                                        \
            uint32 aH0 = par ? t01 : t00;                                    \
            uint32 aH1 = par ? t03 : t02;                                    \
            uint32 aH2 = par ? t11 : t10;                                    \
            uint32 aH3 = par ? t13 : t12;                                    \
            _Pragma("unroll")                                                \
            for (int np = 0; np < 3; np++)                                   \
                MMA_TF32(y[ms][np][0], y[ms][np][1], y[ms][np][2],           \
                         y[ms][np][3], aH0, aH1, aH2, aH3,                   \
                         bB[np][0], bB[np][1]);                              \
        }                                                                    \
    }                                                                        \
} while(0)

// ---------------------------------------------------------------------------
// Kernel 0: one-time head-weight folding (R10 version, unchanged).
// ---------------------------------------------------------------------------
__global__ __launch_bounds__(640) void prep_kernel(
    const float* __restrict__ llW, const float* __restrict__ llb,
    const float* __restrict__ flW)
{
    const int tid = threadIdx.x;
    if (tid < 2*SEQ*NB){
        const bool two = tid >= SEQ*NB;
        const int idx = two ? tid - SEQ*NB : tid;
        const int s = idx/NB, c = idx - s*NB;
        const float* fw = flW + (two ? AMAX*NB : 0) + c;
        const float* lw = llW + s*AMAX;
        float a0 = 0.f, a1 = 0.f, a2 = 0.f, a3 = 0.f;
        #pragma unroll 4
        for (int j = 0; j < AMAX; j += 4){
            a0 += lw[j]  *fw[j*NB];
            a1 += lw[j+1]*fw[(j+1)*NB];
            a2 += lw[j+2]*fw[(j+2)*NB];
            a3 += lw[j+3]*fw[(j+3)*NB];
        }
        (two ? g_M2 : g_M1)[idx] = (a0 + a1) + (a2 + a3);
    } else if (tid >= 608 && tid < 608 + 2*NB){
        const int t = tid - 608;
        const bool two = t >= NB;
        const int c = two ? t - NB : t;
        const float* fw = flW + (two ? AMAX*NB : 0) + c;
        float a0 = 0.f, a1 = 0.f;
        #pragma unroll 4
        for (int j = 0; j < AMAX; j += 2){
            a0 += llb[j]  *fw[j*NB];
            a1 += llb[j+1]*fw[(j+1)*NB];
        }
        (two ? g_c2 : g_c1)[c] = a0 + a1;
    }
    __syncthreads();
    if (tid < 2*NB){
        const bool two = tid >= NB;
        const int c = two ? tid - NB : tid;
        const float* M = two ? g_M2 : g_M1;
        float s = 0.f;
        for (int t = 0; t < SEQ; t++) s += M[t*NB + c];
        (two ? g_S2 : g_S1)[c] = s;
    }
}

// ---------------------------------------------------------------------------
// Kernel 1: per-layer  y = x + Attn(LN1(x)); dual write. 1024 threads
// (R13-measured win: 15.0us, occ 76%).
// ---------------------------------------------------------------------------
__global__ __launch_bounds__(1024) void attn_kernel(
    const float* __restrict__ x_in,
    float* __restrict__ outA, float* __restrict__ outB,
    const float* __restrict__ Wq, const float* __restrict__ bq,
    const float* __restrict__ Wk, const float* __restrict__ bk,
    const float* __restrict__ Wv, const float* __restrict__ bv,
    const float* __restrict__ Wo, const float* __restrict__ bo,
    const float* __restrict__ ln_a, const float* __restrict__ ln_b,
    const int* __restrict__ mask, int layer)
{
    __shared__ float xs[SEQ*DIM], x2[SEQ*DIM];
    __shared__ float qs[SEQ*DIM], ks[SEQ*DIM], vs[SEQ*DIM], os[SEQ*DIM];
    __shared__ float sc[HEADS*SEQ*SEQ];
    __shared__ float w[4][DIM*DIM];
    __shared__ float bb[4][DIM];
    __shared__ float lna[DIM], lnb[DIM];
    __shared__ float maskadd[SEQ];

    const int b = blockIdx.x, tid = threadIdx.x;
    const int wrp = tid >> 5, lane = tid & 31;
    const int woff = layer*DIM*DIM;
    for (int i = tid; i < DIM*DIM; i += 1024){
        w[0][i] = Wq[woff+i]; w[1][i] = Wk[woff+i];
        w[2][i] = Wv[woff+i]; w[3][i] = Wo[woff+i];
    }
    if (tid < DIM){
        bb[0][tid] = bq[layer*DIM+tid]; bb[1][tid] = bk[layer*DIM+tid];
        bb[2][tid] = bv[layer*DIM+tid]; bb[3][tid] = bo[layer*DIM+tid];
        lna[tid] = ln_a[layer*DIM+tid]; lnb[tid] = ln_b[layer*DIM+tid];
    }
    for (int i = tid; i < SEQ*DIM; i += 1024) xs[i] = x_in[b*SEQ*DIM + i];
    if (tid >= 64 && tid < 64+SEQ){
        int t = tid - 64;
        maskadd[t] = (mask[b*SEQ + t] == 0) ? -1e9f : 0.f;
    }
    __syncthreads();

    if (tid < SEQ){
        const float* xr = &xs[tid*DIM];
        float mu = 0.f;
        #pragma unroll
        for (int k = 0; k < DIM; k++) mu += xr[k];
        mu *= (1.f/DIM);
        float var = 0.f;
        #pragma unroll
        for (int k = 0; k < DIM; k++){ float d = xr[k]-mu; var += d*d; }
        float sd = sqrtf(var * (1.f/(DIM-1)));
        float inv = 1.f/(sd + LNEPS);
        #pragma unroll
        for (int k = 0; k < DIM; k++) x2[tid*DIM+k] = lna[k]*(xr[k]-mu)*inv + lnb[k];
    }
    __syncthreads();

    for (int idx = tid; idx < 3*SEQ*DIM; idx += 1024){
        int wsel = idx/(SEQ*DIM);
        int rc = idx - wsel*SEQ*DIM;
        int r = rc/DIM, c = rc - r*DIM;
        const float* wm = &w[wsel][c];
        const float* xr = &x2[r*DIM];
        float a0 = bb[wsel][c], a1 = 0.f;
        #pragma unroll
        for (int k = 0; k < DIM; k += 2){
            a0 += xr[k]  *wm[k*DIM];
            a1 += xr[k+1]*wm[(k+1)*DIM];
        }
        (wsel==0 ? qs : (wsel==1 ? ks : vs))[rc] = a0 + a1;
    }
    __syncthreads();

    const float scale = rsqrtf((float)DKH);
    for (int row = wrp; row < HEADS*SEQ; row += 32){
        int h = row/SEQ, s = row - h*SEQ;
        const float* qp = &qs[s*DIM + h*DKH];
        float q0 = qp[0], q1 = qp[1], q2 = qp[2], q3 = qp[3], q4 = qp[4], q5 = qp[5];

        float e0, e1 = 0.f;
        {
            const float* kp = &ks[lane*DIM + h*DKH];
            float a = q0*kp[0] + q1*kp[1] + q2*kp[2] + q3*kp[3] + q4*kp[4] + q5*kp[5];
            e0 = __expf(a*scale + maskadd[lane]);
        }
        const int t1 = lane + 32;
        if (t1 < SEQ){
            const float* kp = &ks[t1*DIM + h*DKH];
            float a = q0*kp[0] + q1*kp[1] + q2*kp[2] + q3*kp[3] + q4*kp[4] + q5*kp[5];
            e1 = __expf(a*scale + maskadd[t1]);
        }
        float ssum = e0 + e1;
        #pragma unroll
        for (int off = 16; off; off >>= 1)
            ssum += __shfl_xor_sync(0xffffffffu, ssum, off);
        float inv = 1.f/ssum;
        sc[row*SEQ + lane] = e0*inv;
        if (t1 < SEQ) sc[row*SEQ + t1] = e1*inv;
    }
    __syncthreads();

    for (int idx = tid; idx < SEQ*DIM; idx += 1024){
        int r = idx/DIM, j = idx - r*DIM;
        int h = j/DKH;
        const float* prow = &sc[(h*SEQ + r)*SEQ];
        const float* vp = &vs[j];
        float a0 = 0.f, a1 = 0.f;
        #pragma unroll 2
        for (int t = 0; t < SEQ-1; t += 2){
            a0 += prow[t]  *vp[t*DIM];
            a1 += prow[t+1]*vp[(t+1)*DIM];
        }
        os[idx] = a0 + a1 + prow[SEQ-1]*vp[(SEQ-1)*DIM];
    }
    __syncthreads();

    for (int idx = tid; idx < SEQ*DIM; idx += 1024){
        int r = idx/DIM, c = idx - r*DIM;
        const float* wp = &w[3][c];
        const float* op = &os[r*DIM];
        float a0 = xs[idx] + bb[3][c], a1 = 0.f;
        #pragma unroll
        for (int k = 0; k < DIM; k += 2){
            a0 += op[k]  *wp[k*DIM];
            a1 += op[k+1]*wp[(k+1)*DIM];
        }
        float acc = a0 + a1;
        outA[b*SEQ*DIM + idx] = acc;
        outB[b*SEQ*DIM + idx] = acc;
    }
}

// ---------------------------------------------------------------------------
// Kernel 2: tensor-core FF, R10 config (128 thr, 128 rows, grid 86x8) with
// register-prefetch of chunk 1 staged behind chunk 0's MMA loop.
// ---------------------------------------------------------------------------
__global__ __launch_bounds__(128) void ff_kernel(
    const float* __restrict__ x_in, float* __restrict__ x_acc,
    const float* __restrict__ W1g, const float* __restrict__ b1g,
    const float* __restrict__ W2g, const float* __restrict__ b2g,
    const float* __restrict__ ln_a, const float* __restrict__ ln_b, int layer)
{
    __shared__ float  ln2x[128][28];
    __shared__ uint32 w1s[24*136];
    __shared__ uint32 w2t[24*132];
    __shared__ float  b1s[FCH];
    __shared__ float  sLa[DIM], sLb[DIM];

    const int tid = threadIdx.x;
    const int wrp = tid >> 5, lane = tid & 31;
    const int g = lane >> 2, q = lane & 3;
    const int bx = blockIdx.x, by = blockIdx.y;

    if (tid < DIM){ sLa[tid] = ln_a[layer*DIM+tid]; sLb[tid] = ln_b[layer*DIM+tid]; }
    // zero the pad rows once
    for (int i = tid; i < 6*(FCH/4); i += 128){
        int k = DIM + i/(FCH/4), f4 = (i % (FCH/4))*4;
        *reinterpret_cast<uint4*>(&w1s[k*136 + f4]) = make_uint4(0u,0u,0u,0u);
        *reinterpret_cast<uint4*>(&w2t[k*132 + f4]) = make_uint4(0u,0u,0u,0u);
    }
    __syncthreads();

    {
        const int m = bx*128 + tid;
        float xr[DIM];
        #pragma unroll
        for (int k2 = 0; k2 < DIM/2; k2++){
            float2 t = *reinterpret_cast<const float2*>(&x_in[m*DIM + 2*k2]);
            xr[2*k2] = t.x; xr[2*k2+1] = t.y;
        }
        float mu = 0.f;
        #pragma unroll
        for (int k = 0; k < DIM; k++) mu += xr[k];
        mu *= (1.f/DIM);
        float var = 0.f;
        #pragma unroll
        for (int k = 0; k < DIM; k++){ float d = xr[k]-mu; var += d*d; }
        float inv = 1.f/(sqrtf(var*(1.f/(DIM-1))) + LNEPS);
        #pragma unroll
        for (int k = 0; k < DIM; k++) ln2x[tid][k] = sLa[k]*(xr[k]-mu)*inv + sLb[k];
        #pragma unroll
        for (int k = DIM; k < 24; k++) ln2x[tid][k] = 0.f;
    }
    __syncthreads();

    uint32 aU[2][3][4];
    #pragma unroll
    for (int ms = 0; ms < 2; ms++){
        const int rA = wrp*32 + ms*16 + g;
        const int rB = rA + 8;
        #pragma unroll
        for (int ks = 0; ks < 3; ks++){
            aU[ms][ks][0] = tf32cvt(ln2x[rA][8*ks + q]);
            aU[ms][ks][1] = tf32cvt(ln2x[rB][8*ks + q]);
            aU[ms][ks][2] = tf32cvt(ln2x[rA][8*ks + q + 4]);
            aU[ms][ks][3] = tf32cvt(ln2x[rB][8*ks + q + 4]);
        }
    }

    float y[2][3][4];
    #pragma unroll
    for (int np = 0; np < 3; np++){
        const int c0 = np*8 + 2*q, c1 = c0 + 1;
        float bz0 = (by == 0 && c0 < DIM) ? __ldg(&b2g[layer*DIM + c0]) : 0.f;
        float bz1 = (by == 0 && c1 < DIM) ? __ldg(&b2g[layer*DIM + c1]) : 0.f;
        #pragma unroll
        for (int ms = 0; ms < 2; ms++){
            y[ms][np][0] = bz0; y[ms][np][1] = bz1;
            y[ms][np][2] = bz0; y[ms][np][3] = bz1;
        }
    }

    // ---- stage chunk 0 directly (R10 path) ----
    const int fb0 = by*FBLK;
    for (int i = tid; i < DIM*(FCH/4); i += 128){
        int k = i/(FCH/4), f4 = (i - k*(FCH/4))*4;
        float4 v = *reinterpret_cast<const float4*>(
            &W1g[layer*DIM*DFF + k*DFF + fb0 + f4]);
        *reinterpret_cast<uint4*>(&w1s[k*136 + f4]) =
            make_uint4(tf32cvt(v.x), tf32cvt(v.y), tf32cvt(v.z), tf32cvt(v.w));
    }
    for (int i = tid; i < FCH*(DIM/2); i += 128){
        int f = i/(DIM/2), d2 = (i - f*(DIM/2))*2;
        float2 v = *reinterpret_cast<const float2*>(
            &W2g[layer*DFF*DIM + (fb0 + f)*DIM + d2]);
        w2t[d2*132 + f]     = tf32cvt(v.x);
        w2t[(d2+1)*132 + f] = tf32cvt(v.y);
    }
    b1s[tid] = b1g[layer*DFF + fb0 + tid];
    __syncthreads();

    // ---- prefetch chunk 1 into registers (overlaps with chunk-0 MMA) ----
    const int fb1 = fb0 + FCH;
    float4 pw1[5];
    float2 pw2[9];
    float  pb1 = b1g[layer*DFF + fb1 + tid];
    #pragma unroll
    for (int it = 0; it < 5; it++){
        int i = tid + it*128;
        if (i < DIM*(FCH/4)){
            int k = i/(FCH/4), f4 = (i - k*(FCH/4))*4;
            pw1[it] = *reinterpret_cast<const float4*>(
                &W1g[layer*DIM*DFF + k*DFF + fb1 + f4]);
        }
    }
    #pragma unroll
    for (int it = 0; it < 9; it++){
        int i = tid + it*128;
        int f = i/(DIM/2), d2 = (i - f*(DIM/2))*2;
        pw2[it] = *reinterpret_cast<const float2*>(
            &W2g[layer*DFF*DIM + (fb1 + f)*DIM + d2]);
    }

    // ---- chunk 0 MMA ----
    MMA_CHUNK();
    __syncthreads();

    // ---- commit prefetched chunk 1 to smem ----
    #pragma unroll
    for (int it = 0; it < 5; it++){
        int i = tid + it*128;
        if (i < DIM*(FCH/4)){
            int k = i/(FCH/4), f4 = (i - k*(FCH/4))*4;
            *reinterpret_cast<uint4*>(&w1s[k*136 + f4]) =
                make_uint4(tf32cvt(pw1[it].x), tf32cvt(pw1[it].y),
                           tf32cvt(pw1[it].z), tf32cvt(pw1[it].w));
        }
    }
    #pragma unroll
    for (int it = 0; it < 9; it++){
        int i = tid + it*128;
        int f = i/(DIM/2), d2 = (i - f*(DIM/2))*2;
        w2t[d2*132 + f]     = tf32cvt(pw2[it].x);
        w2t[(d2+1)*132 + f] = tf32cvt(pw2[it].y);
    }
    b1s[tid] = pb1;
    __syncthreads();

    // ---- chunk 1 MMA ----
    MMA_CHUNK();

    #pragma unroll
    for (int ms = 0; ms < 2; ms++){
        const int r0 = bx*128 + wrp*32 + ms*16 + g;
        const int r1 = r0 + 8;
        #pragma unroll
        for (int np = 0; np < 3; np++){
            const int c0 = np*8 + 2*q, c1 = c0 + 1;
            if (c0 < DIM){
                atomicAdd(&x_acc[r0*DIM + c0], y[ms][np][0]);
                atomicAdd(&x_acc[r1*DIM + c0], y[ms][np][2]);
            }
            if (c1 < DIM){
                atomicAdd(&x_acc[r0*DIM + c1], y[ms][np][1]);
                atomicAdd(&x_acc[r1*DIM + c1], y[ms][np][3]);
            }
        }
    }
}

// ---------------------------------------------------------------------------
// Kernel 3: final head via folded weights (unchanged).
// ---------------------------------------------------------------------------
__global__ __launch_bounds__(256) void final_kernel(
    const float* __restrict__ x,
    const float* __restrict__ ll2W, const float* __restrict__ ll2b,
    const float* __restrict__ flb,
    float* __restrict__ out)
{
    __shared__ float xb[SEQ*DIM];
    __shared__ float sll2W[DIM*AMAX];
    __shared__ float sll2b[AMAX];
    __shared__ float sM1[SEQ*NB], sM2[SEQ*NB];
    __shared__ float sG1[DIM*NB], sG2[DIM*NB];
    __shared__ __align__(16) float Ps[AMAX*NB];
    __shared__ __align__(16) float QF[AMAX*NB];
    __shared__ float sc1[NB], sc2[NB], sS1[NB], sS2[NB], sflb[NB];

    const int b = blockIdx.x, tid = threadIdx.x;

    for (int i = tid; i < SEQ*DIM; i += 256) xb[i] = x[b*SEQ*DIM + i];
    for (int i = tid; i < DIM*AMAX; i += 256) sll2W[i] = ll2W[i];
    if (tid < AMAX) sll2b[tid] = ll2b[tid];
    for (int i = tid; i < SEQ*NB; i += 256){ sM1[i] = g_M1[i]; sM2[i] = g_M2[i]; }
    if (tid < NB){
        sc1[tid] = g_c1[tid]; sc2[tid] = g_c2[tid];
        sS1[tid] = g_S1[tid]; sS2[tid] = g_S2[tid];
        sflb[tid] = flb[tid];
    }
    __syncthreads();

    if (tid < 2*DIM*NB){
        const bool two = (tid >= DIM*NB);
        const int kc = two ? tid - DIM*NB : tid;
        const int k = kc/NB, c = kc - k*NB;
        const float* M = two ? sM2 : sM1;
        float acc = 0.f;
        for (int s = 0; s < SEQ; s++) acc += xb[s*DIM + k]*M[s*NB + c];
        (two ? sG2 : sG1)[kc] = acc;
    }
    __syncthreads();

    for (int idx = tid; idx < 2*AMAX*NB; idx += 256){
        const bool two = (idx >= AMAX*NB);
        const int ac = two ? idx - AMAX*NB : idx;
        const int a = ac/NB, c = ac - a*NB;
        const float* G = two ? sG2 : sG1;
        float acc = two ? (sll2b[a]*sS2[c] + sc2[c] + sflb[c])
                        : (sll2b[a]*sS1[c] + sc1[c]);
        #pragma unroll
        for (int k = 0; k < DIM; k++) acc += sll2W[k*AMAX + a]*G[k*NB + c];
        (two ? QF : Ps)[ac] = acc;
    }
    __syncthreads();

    float4* out4 = reinterpret_cast<float4*>(out + (size_t)b * (AMAX*AMAX*NB));
    const int NV = AMAX*AMAX*NB/4;
    const int VPI = AMAX*NB/4;
    for (int idx4 = tid; idx4 < NV; idx4 += 256){
        int i = idx4 / VPI;
        int rem4 = (idx4 - i*VPI) * 4;
        float4 qv = *reinterpret_cast<const float4*>(&QF[rem4]);
        const float* Pi = &Ps[i*NB];
        int c = rem4 % NB;
        qv.x += Pi[c];       c++; if (c == NB) c = 0;
        qv.y += Pi[c];       c++; if (c == NB) c = 0;
        qv.z += Pi[c];       c++; if (c == NB) c = 0;
        qv.w += Pi[c];
        out4[idx4] = qv;
    }
}

// ---------------------------------------------------------------------------
extern "C" void kernel_launch(void* const* d_in, const int* in_sizes, int n_in,
                              void* d_out, int out_size)
{
    const float *src, *Wq, *bq, *Wk, *bk, *Wv, *bv, *Wo, *bo;
    const float *ln1a, *ln1b, *ln2a, *ln2b, *ffW1, *ffb1, *ffW2, *ffb2;
    const float *ll2W, *ll2b, *llW, *llb, *flW, *flb;
    const int* mask;

    if (in_sizes[1] == NROWS){
        src  = (const float*)d_in[0];
        mask = (const int*)  d_in[1];
        Wq   = (const float*)d_in[3];  bq   = (const float*)d_in[4];
        Wk   = (const float*)d_in[5];  bk   = (const float*)d_in[6];
        Wv   = (const float*)d_in[7];  bv   = (const float*)d_in[8];
        Wo   = (const float*)d_in[9];  bo   = (const float*)d_in[10];
        ln1a = (const float*)d_in[11]; ln1b = (const float*)d_in[12];
        ln2a = (const float*)d_in[13]; ln2b = (const float*)d_in[14];
        ffW1 = (const float*)d_in[15]; ffb1 = (const float*)d_in[16];
        ffW2 = (const float*)d_in[17]; ffb2 = (const float*)d_in[18];
        ll2W = (const float*)d_in[19]; ll2b = (const float*)d_in[20];
        llW  = (const float*)d_in[21]; llb  = (const float*)d_in[22];
        flW  = (const float*)d_in[23]; flb  = (const float*)d_in[24];
    } else {
        src  = (const float*)d_in[0];
        Wq   = (const float*)d_in[1];  bq   = (const float*)d_in[2];
        Wk   = (const float*)d_in[3];  bk   = (const float*)d_in[4];
        Wv   = (const float*)d_in[5];  bv   = (const float*)d_in[6];
        Wo   = (const float*)d_in[7];  bo   = (const float*)d_in[8];
        ln1a = (const float*)d_in[9];  ln1b = (const float*)d_in[10];
        ln2a = (const float*)d_in[11]; ln2b = (const float*)d_in[12];
        ffW1 = (const float*)d_in[13]; ffb1 = (const float*)d_in[14];
        ffW2 = (const float*)d_in[15]; ffb2 = (const float*)d_in[16];
        ll2W = (const float*)d_in[17]; ll2b = (const float*)d_in[18];
        llW  = (const float*)d_in[19]; llb  = (const float*)d_in[20];
        flW  = (const float*)d_in[21]; flb  = (const float*)d_in[22];
        mask = (const int*)  d_in[23];
    }

    float *A, *B;
    cudaGetSymbolAddress((void**)&A, g_bufA);
    cudaGetSymbolAddress((void**)&B, g_bufB);

    prep_kernel<<<1, 640>>>(llW, llb, flW);

    const float* cur = src;
    for (int l = 0; l < NLAYERS; l++){
        attn_kernel<<<BATCH, 1024>>>(cur, A, B, Wq, bq, Wk, bk, Wv, bv, Wo, bo,
                                     ln1a, ln1b, mask, l);
        ff_kernel<<<dim3(NROWS/128, FSPLIT), 128>>>(A, B, ffW1, ffb1, ffW2, ffb2,
                                                    ln2a, ln2b, l);
        cur = B;
        float* tmp = A; A = B; B = tmp;
    }

    final_kernel<<<BATCH, 256>>>(cur, ll2W, ll2b, flb, (float*)d_out);
}

// round 15
// speedup vs baseline: 1.0833x; 1.0833x over previous
#include <cuda_runtime.h>
#include <cstdint>

#define SEQ 43
#define DIM 18
#define NLAYERS 6
#define HEADS 3
#define DKH 6
#define DFF 2048
#define BATCH 256
#define AMAX 128
#define NB 7
#define NROWS (BATCH*SEQ)   /* 11008 = 86*128 */
#define LNEPS 1e-6f

#define FSPLIT 8             /* f-splits for ff grid.y */
#define FBLK 256             /* f per block */
#define FCH 128              /* f per staging chunk */

typedef unsigned int uint32;

__device__ float g_bufA[NROWS*DIM];
__device__ float g_bufB[NROWS*DIM];
__device__ float g_M1[SEQ*NB], g_M2[SEQ*NB];
__device__ float g_S1[NB], g_S2[NB], g_c1[NB], g_c2[NB];

__device__ __forceinline__ uint32 tf32cvt(float f){
    uint32 u; asm("cvt.rna.tf32.f32 %0, %1;" : "=r"(u) : "f"(f)); return u;
}

#define MMA_TF32(d0,d1,d2,d3,a0,a1,a2,a3,b0,b1)                          \
    asm volatile("mma.sync.aligned.m16n8k8.row.col.f32.tf32.tf32.f32 "   \
        "{%0,%1,%2,%3}, {%4,%5,%6,%7}, {%8,%9}, {%0,%1,%2,%3};"          \
        : "+f"(d0), "+f"(d1), "+f"(d2), "+f"(d3)                          \
        : "r"(a0), "r"(a1), "r"(a2), "r"(a3), "r"(b0), "r"(b1))

// ---------------------------------------------------------------------------
// Kernel 0: one-time head-weight folding (R10 version, unchanged).
// ---------------------------------------------------------------------------
__global__ __launch_bounds__(640) void prep_kernel(
    const float* __restrict__ llW, const float* __restrict__ llb,
    const float* __restrict__ flW)
{
    const int tid = threadIdx.x;
    if (tid < 2*SEQ*NB){
        const bool two = tid >= SEQ*NB;
        const int idx = two ? tid - SEQ*NB : tid;
        const int s = idx/NB, c = idx - s*NB;
        const float* fw = flW + (two ? AMAX*NB : 0) + c;
        const float* lw = llW + s*AMAX;
        float a0 = 0.f, a1 = 0.f, a2 = 0.f, a3 = 0.f;
        #pragma unroll 4
        for (int j = 0; j < AMAX; j += 4){
            a0 += lw[j]  *fw[j*NB];
            a1 += lw[j+1]*fw[(j+1)*NB];
            a2 += lw[j+2]*fw[(j+2)*NB];
            a3 += lw[j+3]*fw[(j+3)*NB];
        }
        (two ? g_M2 : g_M1)[idx] = (a0 + a1) + (a2 + a3);
    } else if (tid >= 608 && tid < 608 + 2*NB){
        const int t = tid - 608;
        const bool two = t >= NB;
        const int c = two ? t - NB : t;
        const float* fw = flW + (two ? AMAX*NB : 0) + c;
        float a0 = 0.f, a1 = 0.f;
        #pragma unroll 4
        for (int j = 0; j < AMAX; j += 2){
            a0 += llb[j]  *fw[j*NB];
            a1 += llb[j+1]*fw[(j+1)*NB];
        }
        (two ? g_c2 : g_c1)[c] = a0 + a1;
    }
    __syncthreads();
    if (tid < 2*NB){
        const bool two = tid >= NB;
        const int c = two ? tid - NB : tid;
        const float* M = two ? g_M2 : g_M1;
        float s = 0.f;
        for (int t = 0; t < SEQ; t++) s += M[t*NB + c];
        (two ? g_S2 : g_S1)[c] = s;
    }
}

// ---------------------------------------------------------------------------
// Kernel 1: per-layer  y = x + Attn(LN1(x)); dual write. 1024 threads
// (R13/R14-measured: 15.0us, occ ~80%). Unchanged.
// ---------------------------------------------------------------------------
__global__ __launch_bounds__(1024) void attn_kernel(
    const float* __restrict__ x_in,
    float* __restrict__ outA, float* __restrict__ outB,
    const float* __restrict__ Wq, const float* __restrict__ bq,
    const float* __restrict__ Wk, const float* __restrict__ bk,
    const float* __restrict__ Wv, const float* __restrict__ bv,
    const float* __restrict__ Wo, const float* __restrict__ bo,
    const float* __restrict__ ln_a, const float* __restrict__ ln_b,
    const int* __restrict__ mask, int layer)
{
    __shared__ float xs[SEQ*DIM], x2[SEQ*DIM];
    __shared__ float qs[SEQ*DIM], ks[SEQ*DIM], vs[SEQ*DIM], os[SEQ*DIM];
    __shared__ float sc[HEADS*SEQ*SEQ];
    __shared__ float w[4][DIM*DIM];
    __shared__ float bb[4][DIM];
    __shared__ float lna[DIM], lnb[DIM];
    __shared__ float maskadd[SEQ];

    const int b = blockIdx.x, tid = threadIdx.x;
    const int wrp = tid >> 5, lane = tid & 31;
    const int woff = layer*DIM*DIM;
    for (int i = tid; i < DIM*DIM; i += 1024){
        w[0][i] = Wq[woff+i]; w[1][i] = Wk[woff+i];
        w[2][i] = Wv[woff+i]; w[3][i] = Wo[woff+i];
    }
    if (tid < DIM){
        bb[0][tid] = bq[layer*DIM+tid]; bb[1][tid] = bk[layer*DIM+tid];
        bb[2][tid] = bv[layer*DIM+tid]; bb[3][tid] = bo[layer*DIM+tid];
        lna[tid] = ln_a[layer*DIM+tid]; lnb[tid] = ln_b[layer*DIM+tid];
    }
    for (int i = tid; i < SEQ*DIM; i += 1024) xs[i] = x_in[b*SEQ*DIM + i];
    if (tid >= 64 && tid < 64+SEQ){
        int t = tid - 64;
        maskadd[t] = (mask[b*SEQ + t] == 0) ? -1e9f : 0.f;
    }
    __syncthreads();

    if (tid < SEQ){
        const float* xr = &xs[tid*DIM];
        float mu = 0.f;
        #pragma unroll
        for (int k = 0; k < DIM; k++) mu += xr[k];
        mu *= (1.f/DIM);
        float var = 0.f;
        #pragma unroll
        for (int k = 0; k < DIM; k++){ float d = xr[k]-mu; var += d*d; }
        float sd = sqrtf(var * (1.f/(DIM-1)));
        float inv = 1.f/(sd + LNEPS);
        #pragma unroll
        for (int k = 0; k < DIM; k++) x2[tid*DIM+k] = lna[k]*(xr[k]-mu)*inv + lnb[k];
    }
    __syncthreads();

    for (int idx = tid; idx < 3*SEQ*DIM; idx += 1024){
        int wsel = idx/(SEQ*DIM);
        int rc = idx - wsel*SEQ*DIM;
        int r = rc/DIM, c = rc - r*DIM;
        const float* wm = &w[wsel][c];
        const float* xr = &x2[r*DIM];
        float a0 = bb[wsel][c], a1 = 0.f;
        #pragma unroll
        for (int k = 0; k < DIM; k += 2){
            a0 += xr[k]  *wm[k*DIM];
            a1 += xr[k+1]*wm[(k+1)*DIM];
        }
        (wsel==0 ? qs : (wsel==1 ? ks : vs))[rc] = a0 + a1;
    }
    __syncthreads();

    const float scale = rsqrtf((float)DKH);
    for (int row = wrp; row < HEADS*SEQ; row += 32){
        int h = row/SEQ, s = row - h*SEQ;
        const float* qp = &qs[s*DIM + h*DKH];
        float q0 = qp[0], q1 = qp[1], q2 = qp[2], q3 = qp[3], q4 = qp[4], q5 = qp[5];

        float e0, e1 = 0.f;
        {
            const float* kp = &ks[lane*DIM + h*DKH];
            float a = q0*kp[0] + q1*kp[1] + q2*kp[2] + q3*kp[3] + q4*kp[4] + q5*kp[5];
            e0 = __expf(a*scale + maskadd[lane]);
        }
        const int t1 = lane + 32;
        if (t1 < SEQ){
            const float* kp = &ks[t1*DIM + h*DKH];
            float a = q0*kp[0] + q1*kp[1] + q2*kp[2] + q3*kp[3] + q4*kp[4] + q5*kp[5];
            e1 = __expf(a*scale + maskadd[t1]);
        }
        float ssum = e0 + e1;
        #pragma unroll
        for (int off = 16; off; off >>= 1)
            ssum += __shfl_xor_sync(0xffffffffu, ssum, off);
        float inv = 1.f/ssum;
        sc[row*SEQ + lane] = e0*inv;
        if (t1 < SEQ) sc[row*SEQ + t1] = e1*inv;
    }
    __syncthreads();

    for (int idx = tid; idx < SEQ*DIM; idx += 1024){
        int r = idx/DIM, j = idx - r*DIM;
        int h = j/DKH;
        const float* prow = &sc[(h*SEQ + r)*SEQ];
        const float* vp = &vs[j];
        float a0 = 0.f, a1 = 0.f;
        #pragma unroll 2
        for (int t = 0; t < SEQ-1; t += 2){
            a0 += prow[t]  *vp[t*DIM];
            a1 += prow[t+1]*vp[(t+1)*DIM];
        }
        os[idx] = a0 + a1 + prow[SEQ-1]*vp[(SEQ-1)*DIM];
    }
    __syncthreads();

    for (int idx = tid; idx < SEQ*DIM; idx += 1024){
        int r = idx/DIM, c = idx - r*DIM;
        const float* wp = &w[3][c];
        const float* op = &os[r*DIM];
        float a0 = xs[idx] + bb[3][c], a1 = 0.f;
        #pragma unroll
        for (int k = 0; k < DIM; k += 2){
            a0 += op[k]  *wp[k*DIM];
            a1 += op[k+1]*wp[(k+1)*DIM];
        }
        float acc = a0 + a1;
        outA[b*SEQ*DIM + idx] = acc;
        outB[b*SEQ*DIM + idx] = acc;
    }
}

// ---------------------------------------------------------------------------
// Kernel 2: tensor-core FF — R10 EXACT (128 thr, 128 rows, grid 86x8,
// vectorized staging, 2-chunk loop). Measured ~27us/layer; do not perturb.
// ---------------------------------------------------------------------------
__global__ __launch_bounds__(128) void ff_kernel(
    const float* __restrict__ x_in, float* __restrict__ x_acc,
    const float* __restrict__ W1g, const float* __restrict__ b1g,
    const float* __restrict__ W2g, const float* __restrict__ b2g,
    const float* __restrict__ ln_a, const float* __restrict__ ln_b, int layer)
{
    __shared__ float  ln2x[128][28];
    __shared__ uint32 w1s[24*136];
    __shared__ uint32 w2t[24*132];
    __shared__ float  b1s[FCH];
    __shared__ float  sLa[DIM], sLb[DIM];

    const int tid = threadIdx.x;
    const int wrp = tid >> 5, lane = tid & 31;
    const int g = lane >> 2, q = lane & 3;
    const int bx = blockIdx.x, by = blockIdx.y;

    if (tid < DIM){ sLa[tid] = ln_a[layer*DIM+tid]; sLb[tid] = ln_b[layer*DIM+tid]; }
    // zero the pad rows of w1s/w2t ONCE (they never change)
    for (int i = tid; i < 6*(FCH/4); i += 128){
        int k = DIM + i/(FCH/4), f4 = (i % (FCH/4))*4;
        *reinterpret_cast<uint4*>(&w1s[k*136 + f4]) = make_uint4(0u,0u,0u,0u);
        *reinterpret_cast<uint4*>(&w2t[k*132 + f4]) = make_uint4(0u,0u,0u,0u);
    }
    __syncthreads();

    {
        const int m = bx*128 + tid;
        float xr[DIM];
        #pragma unroll
        for (int k2 = 0; k2 < DIM/2; k2++){
            float2 t = *reinterpret_cast<const float2*>(&x_in[m*DIM + 2*k2]);
            xr[2*k2] = t.x; xr[2*k2+1] = t.y;
        }
        float mu = 0.f;
        #pragma unroll
        for (int k = 0; k < DIM; k++) mu += xr[k];
        mu *= (1.f/DIM);
        float var = 0.f;
        #pragma unroll
        for (int k = 0; k < DIM; k++){ float d = xr[k]-mu; var += d*d; }
        float inv = 1.f/(sqrtf(var*(1.f/(DIM-1))) + LNEPS);
        #pragma unroll
        for (int k = 0; k < DIM; k++) ln2x[tid][k] = sLa[k]*(xr[k]-mu)*inv + sLb[k];
        #pragma unroll
        for (int k = DIM; k < 24; k++) ln2x[tid][k] = 0.f;
    }
    __syncthreads();

    uint32 aU[2][3][4];
    #pragma unroll
    for (int ms = 0; ms < 2; ms++){
        const int rA = wrp*32 + ms*16 + g;
        const int rB = rA + 8;
        #pragma unroll
        for (int ks = 0; ks < 3; ks++){
            aU[ms][ks][0] = tf32cvt(ln2x[rA][8*ks + q]);
            aU[ms][ks][1] = tf32cvt(ln2x[rB][8*ks + q]);
            aU[ms][ks][2] = tf32cvt(ln2x[rA][8*ks + q + 4]);
            aU[ms][ks][3] = tf32cvt(ln2x[rB][8*ks + q + 4]);
        }
    }

    float y[2][3][4];
    #pragma unroll
    for (int np = 0; np < 3; np++){
        const int c0 = np*8 + 2*q, c1 = c0 + 1;
        float bz0 = (by == 0 && c0 < DIM) ? __ldg(&b2g[layer*DIM + c0]) : 0.f;
        float bz1 = (by == 0 && c1 < DIM) ? __ldg(&b2g[layer*DIM + c1]) : 0.f;
        #pragma unroll
        for (int ms = 0; ms < 2; ms++){
            y[ms][np][0] = bz0; y[ms][np][1] = bz1;
            y[ms][np][2] = bz0; y[ms][np][3] = bz1;
        }
    }

    for (int chunk = 0; chunk < FBLK/FCH; chunk++){
        const int fb = by*FBLK + chunk*FCH;

        // W1: float4 loads, uint4 stores
        for (int i = tid; i < DIM*(FCH/4); i += 128){
            int k = i/(FCH/4), f4 = (i - k*(FCH/4))*4;
            float4 v = *reinterpret_cast<const float4*>(
                &W1g[layer*DIM*DFF + k*DFF + fb + f4]);
            *reinterpret_cast<uint4*>(&w1s[k*136 + f4]) =
                make_uint4(tf32cvt(v.x), tf32cvt(v.y), tf32cvt(v.z), tf32cvt(v.w));
        }
        // W2: float2 loads along d, transposed scatter stores
        for (int i = tid; i < FCH*(DIM/2); i += 128){
            int f = i/(DIM/2), d2 = (i - f*(DIM/2))*2;
            float2 v = *reinterpret_cast<const float2*>(
                &W2g[layer*DFF*DIM + (fb + f)*DIM + d2]);
            w2t[d2*132 + f]     = tf32cvt(v.x);
            w2t[(d2+1)*132 + f] = tf32cvt(v.y);
        }
        b1s[tid] = b1g[layer*DFF + fb + tid];
        __syncthreads();

        for (int f8 = 0; f8 < FCH/8; f8++){
            const int fo = f8*8;
            uint32 bA[3][2];
            #pragma unroll
            for (int ks = 0; ks < 3; ks++){
                bA[ks][0] = w1s[(8*ks + q)*136 + fo + g];
                bA[ks][1] = w1s[(8*ks + q + 4)*136 + fo + g];
            }
            uint32 bB[3][2];
            #pragma unroll
            for (int np = 0; np < 3; np++){
                bB[np][0] = w2t[(np*8 + g)*132 + fo + q];
                bB[np][1] = w2t[(np*8 + g)*132 + fo + q + 4];
            }
            const float hb0 = b1s[fo + 2*q], hb1 = b1s[fo + 2*q + 1];

            #pragma unroll
            for (int ms = 0; ms < 2; ms++){
                float h0 = hb0, h1 = hb1, h2 = hb0, h3 = hb1;
                #pragma unroll
                for (int ks = 0; ks < 3; ks++)
                    MMA_TF32(h0, h1, h2, h3,
                             aU[ms][ks][0], aU[ms][ks][1], aU[ms][ks][2], aU[ms][ks][3],
                             bA[ks][0], bA[ks][1]);
                h0 = fmaxf(h0, 0.f); h1 = fmaxf(h1, 0.f);
                h2 = fmaxf(h2, 0.f); h3 = fmaxf(h3, 0.f);
                uint32 u0 = tf32cvt(h0), u1 = tf32cvt(h1);
                uint32 u2 = tf32cvt(h2), u3 = tf32cvt(h3);

                const int s0 = (lane & ~3) | (q >> 1);
                const int s1 = s0 + 2;
                uint32 t00 = __shfl_sync(0xffffffffu, u0, s0);
                uint32 t01 = __shfl_sync(0xffffffffu, u1, s0);
                uint32 t02 = __shfl_sync(0xffffffffu, u2, s0);
                uint32 t03 = __shfl_sync(0xffffffffu, u3, s0);
                uint32 t10 = __shfl_sync(0xffffffffu, u0, s1);
                uint32 t11 = __shfl_sync(0xffffffffu, u1, s1);
                uint32 t12 = __shfl_sync(0xffffffffu, u2, s1);
                uint32 t13 = __shfl_sync(0xffffffffu, u3, s1);
                const bool par = (q & 1);
                uint32 aH0 = par ? t01 : t00;
                uint32 aH1 = par ? t03 : t02;
                uint32 aH2 = par ? t11 : t10;
                uint32 aH3 = par ? t13 : t12;

                #pragma unroll
                for (int np = 0; np < 3; np++)
                    MMA_TF32(y[ms][np][0], y[ms][np][1], y[ms][np][2], y[ms][np][3],
                             aH0, aH1, aH2, aH3, bB[np][0], bB[np][1]);
            }
        }
        __syncthreads();
    }

    #pragma unroll
    for (int ms = 0; ms < 2; ms++){
        const int r0 = bx*128 + wrp*32 + ms*16 + g;
        const int r1 = r0 + 8;
        #pragma unroll
        for (int np = 0; np < 3; np++){
            const int c0 = np*8 + 2*q, c1 = c0 + 1;
            if (c0 < DIM){
                atomicAdd(&x_acc[r0*DIM + c0], y[ms][np][0]);
                atomicAdd(&x_acc[r1*DIM + c0], y[ms][np][2]);
            }
            if (c1 < DIM){
                atomicAdd(&x_acc[r0*DIM + c1], y[ms][np][1]);
                atomicAdd(&x_acc[r1*DIM + c1], y[ms][np][3]);
            }
        }
    }
}

// ---------------------------------------------------------------------------
// Kernel 3: final head via folded weights (unchanged).
// ---------------------------------------------------------------------------
__global__ __launch_bounds__(256) void final_kernel(
    const float* __restrict__ x,
    const float* __restrict__ ll2W, const float* __restrict__ ll2b,
    const float* __restrict__ flb,
    float* __restrict__ out)
{
    __shared__ float xb[SEQ*DIM];
    __shared__ float sll2W[DIM*AMAX];
    __shared__ float sll2b[AMAX];
    __shared__ float sM1[SEQ*NB], sM2[SEQ*NB];
    __shared__ float sG1[DIM*NB], sG2[DIM*NB];
    __shared__ __align__(16) float Ps[AMAX*NB];
    __shared__ __align__(16) float QF[AMAX*NB];
    __shared__ float sc1[NB], sc2[NB], sS1[NB], sS2[NB], sflb[NB];

    const int b = blockIdx.x, tid = threadIdx.x;

    for (int i = tid; i < SEQ*DIM; i += 256) xb[i] = x[b*SEQ*DIM + i];
    for (int i = tid; i < DIM*AMAX; i += 256) sll2W[i] = ll2W[i];
    if (tid < AMAX) sll2b[tid] = ll2b[tid];
    for (int i = tid; i < SEQ*NB; i += 256){ sM1[i] = g_M1[i]; sM2[i] = g_M2[i]; }
    if (tid < NB){
        sc1[tid] = g_c1[tid]; sc2[tid] = g_c2[tid];
        sS1[tid] = g_S1[tid]; sS2[tid] = g_S2[tid];
        sflb[tid] = flb[tid];
    }
    __syncthreads();

    if (tid < 2*DIM*NB){
        const bool two = (tid >= DIM*NB);
        const int kc = two ? tid - DIM*NB : tid;
        const int k = kc/NB, c = kc - k*NB;
        const float* M = two ? sM2 : sM1;
        float acc = 0.f;
        for (int s = 0; s < SEQ; s++) acc += xb[s*DIM + k]*M[s*NB + c];
        (two ? sG2 : sG1)[kc] = acc;
    }
    __syncthreads();

    for (int idx = tid; idx < 2*AMAX*NB; idx += 256){
        const bool two = (idx >= AMAX*NB);
        const int ac = two ? idx - AMAX*NB : idx;
        const int a = ac/NB, c = ac - a*NB;
        const float* G = two ? sG2 : sG1;
        float acc = two ? (sll2b[a]*sS2[c] + sc2[c] + sflb[c])
                        : (sll2b[a]*sS1[c] + sc1[c]);
        #pragma unroll
        for (int k = 0; k < DIM; k++) acc += sll2W[k*AMAX + a]*G[k*NB + c];
        (two ? QF : Ps)[ac] = acc;
    }
    __syncthreads();

    float4* out4 = reinterpret_cast<float4*>(out + (size_t)b * (AMAX*AMAX*NB));
    const int NV = AMAX*AMAX*NB/4;
    const int VPI = AMAX*NB/4;
    for (int idx4 = tid; idx4 < NV; idx4 += 256){
        int i = idx4 / VPI;
        int rem4 = (idx4 - i*VPI) * 4;
        float4 qv = *reinterpret_cast<const float4*>(&QF[rem4]);
        const float* Pi = &Ps[i*NB];
        int c = rem4 % NB;
        qv.x += Pi[c];       c++; if (c == NB) c = 0;
        qv.y += Pi[c];       c++; if (c == NB) c = 0;
        qv.z += Pi[c];       c++; if (c == NB) c = 0;
        qv.w += Pi[c];
        out4[idx4] = qv;
    }
}

// ---------------------------------------------------------------------------
extern "C" void kernel_launch(void* const* d_in, const int* in_sizes, int n_in,
                              void* d_out, int out_size)
{
    const float *src, *Wq, *bq, *Wk, *bk, *Wv, *bv, *Wo, *bo;
    const float *ln1a, *ln1b, *ln2a, *ln2b, *ffW1, *ffb1, *ffW2, *ffb2;
    const float *ll2W, *ll2b, *llW, *llb, *flW, *flb;
    const int* mask;

    if (in_sizes[1] == NROWS){
        src  = (const float*)d_in[0];
        mask = (const int*)  d_in[1];
        Wq   = (const float*)d_in[3];  bq   = (const float*)d_in[4];
        Wk   = (const float*)d_in[5];  bk   = (const float*)d_in[6];
        Wv   = (const float*)d_in[7];  bv   = (const float*)d_in[8];
        Wo   = (const float*)d_in[9];  bo   = (const float*)d_in[10];
        ln1a = (const float*)d_in[11]; ln1b = (const float*)d_in[12];
        ln2a = (const float*)d_in[13]; ln2b = (const float*)d_in[14];
        ffW1 = (const float*)d_in[15]; ffb1 = (const float*)d_in[16];
        ffW2 = (const float*)d_in[17]; ffb2 = (const float*)d_in[18];
        ll2W = (const float*)d_in[19]; ll2b = (const float*)d_in[20];
        llW  = (const float*)d_in[21]; llb  = (const float*)d_in[22];
        flW  = (const float*)d_in[23]; flb  = (const float*)d_in[24];
    } else {
        src  = (const float*)d_in[0];
        Wq   = (const float*)d_in[1];  bq   = (const float*)d_in[2];
        Wk   = (const float*)d_in[3];  bk   = (const float*)d_in[4];
        Wv   = (const float*)d_in[5];  bv   = (const float*)d_in[6];
        Wo   = (const float*)d_in[7];  bo   = (const float*)d_in[8];
        ln1a = (const float*)d_in[9];  ln1b = (const float*)d_in[10];
        ln2a = (const float*)d_in[11]; ln2b = (const float*)d_in[12];
        ffW1 = (const float*)d_in[13]; ffb1 = (const float*)d_in[14];
        ffW2 = (const float*)d_in[15]; ffb2 = (const float*)d_in[16];
        ll2W = (const float*)d_in[17]; ll2b = (const float*)d_in[18];
        llW  = (const float*)d_in[19]; llb  = (const float*)d_in[20];
        flW  = (const float*)d_in[21]; flb  = (const float*)d_in[22];
        mask = (const int*)  d_in[23];
    }

    float *A, *B;
    cudaGetSymbolAddress((void**)&A, g_bufA);
    cudaGetSymbolAddress((void**)&B, g_bufB);

    prep_kernel<<<1, 640>>>(llW, llb, flW);

    const float* cur = src;
    for (int l = 0; l < NLAYERS; l++){
        attn_kernel<<<BATCH, 1024>>>(cur, A, B, Wq, bq, Wk, bk, Wv, bv, Wo, bo,
                                     ln1a, ln1b, mask, l);
        ff_kernel<<<dim3(NROWS/128, FSPLIT), 128>>>(A, B, ffW1, ffb1, ffW2, ffb2,
                                                    ln2a, ln2b, l);
        cur = B;
        float* tmp = A; A = B; B = tmp;
    }

    final_kernel<<<BATCH, 256>>>(cur, ll2W, ll2b, flb, (float*)d_out);
}